// round 2
// baseline (speedup 1.0000x reference)
#include <cuda_runtime.h>
#include <cstdint>

#define B_  64
#define T_  2048
#define I_  128
#define H_  256
#define C_  64
#define G3  (3 * H_)   // 768

// Scratch: gates buffer reused by both layers; h buffer reused (h0 then h1).
__device__ float g_gates[(size_t)B_ * T_ * G3];  // 402 MB
__device__ float g_h[(size_t)B_ * T_ * H_];      // 134 MB

// ---------------------------------------------------------------------------
// GEMM: C[m,n] = sum_k A[m,k] * B[n,k] + bias[n]
// A: [M,K] row-major, Bm: [N,K] row-major (PyTorch weight layout), C: [M,N]
// BM=128, BN=64, BK=16, 256 threads, 8x4 microtile per thread.
// ---------------------------------------------------------------------------
__global__ void __launch_bounds__(256) gemm_nt(
    const float* __restrict__ A, const float* __restrict__ Bm,
    const float* __restrict__ bias, float* __restrict__ C,
    int M, int N, int K)
{
    const int BM = 128, BN = 64, BK = 16;
    __shared__ float As[BK * BM];
    __shared__ float Bs[BK * BN];

    int tid = threadIdx.x;
    int tx = tid & 15;       // n microtile index (0..15)
    int ty = tid >> 4;       // m microtile index (0..15)
    int m0 = blockIdx.y * BM;
    int n0 = blockIdx.x * BN;

    float acc[8][4];
#pragma unroll
    for (int i = 0; i < 8; i++)
#pragma unroll
        for (int j = 0; j < 4; j++) acc[i][j] = 0.0f;

    for (int kt = 0; kt < K; kt += BK) {
        // Load A tile (128x16 = 512 float4, 2 per thread), transposed to As[k][m]
#pragma unroll
        for (int i = 0; i < 2; i++) {
            int idx = tid + i * 256;
            int row = idx >> 2;
            int c4  = idx & 3;
            float4 v = *(const float4*)&A[(size_t)(m0 + row) * K + kt + c4 * 4];
            As[(c4 * 4 + 0) * BM + row] = v.x;
            As[(c4 * 4 + 1) * BM + row] = v.y;
            As[(c4 * 4 + 2) * BM + row] = v.z;
            As[(c4 * 4 + 3) * BM + row] = v.w;
        }
        // Load B tile (64x16 = 256 float4, 1 per thread), transposed to Bs[k][n]
        {
            int row = tid >> 2;
            int c4  = tid & 3;
            float4 v = *(const float4*)&Bm[(size_t)(n0 + row) * K + kt + c4 * 4];
            Bs[(c4 * 4 + 0) * BN + row] = v.x;
            Bs[(c4 * 4 + 1) * BN + row] = v.y;
            Bs[(c4 * 4 + 2) * BN + row] = v.z;
            Bs[(c4 * 4 + 3) * BN + row] = v.w;
        }
        __syncthreads();

#pragma unroll
        for (int k = 0; k < BK; k++) {
            float4 a0 = *(const float4*)&As[k * BM + ty * 8];
            float4 a1 = *(const float4*)&As[k * BM + ty * 8 + 4];
            float4 bq = *(const float4*)&Bs[k * BN + tx * 4];
            float av[8] = {a0.x, a0.y, a0.z, a0.w, a1.x, a1.y, a1.z, a1.w};
            float bv[4] = {bq.x, bq.y, bq.z, bq.w};
#pragma unroll
            for (int i = 0; i < 8; i++)
#pragma unroll
                for (int j = 0; j < 4; j++)
                    acc[i][j] = fmaf(av[i], bv[j], acc[i][j]);
        }
        __syncthreads();
    }

    float4 bv = *(const float4*)&bias[n0 + tx * 4];
#pragma unroll
    for (int i = 0; i < 8; i++) {
        float4 o;
        o.x = acc[i][0] + bv.x;
        o.y = acc[i][1] + bv.y;
        o.z = acc[i][2] + bv.z;
        o.w = acc[i][3] + bv.w;
        *(float4*)&C[(size_t)(m0 + ty * 8 + i) * N + n0 + tx * 4] = o;
    }
}

// ---------------------------------------------------------------------------
// GRU recurrent scan. 4-CTA clusters; each cluster owns 2 batch elements.
// CTA rank c owns h-columns [c*64, (c+1)*64) i.e. gate rows {j, 256+j, 512+j}.
// W slice resident in SMEM (196 KB), h double-buffered in SMEM, exchanged via
// st.shared::cluster, one cluster barrier per timestep.
// ---------------------------------------------------------------------------
__device__ __forceinline__ float sigmoidf_(float x) {
    return 1.0f / (1.0f + __expf(-x));
}
__device__ __forceinline__ float tanhf_(float x) {
    return 2.0f / (1.0f + __expf(-2.0f * x)) - 1.0f;
}

#define SMEM_WS   196608                       // 64 chunks * 192 rows * 16B
#define SMEM_HB   (SMEM_WS)                    // hbuf: [2][2][256] f32 = 4096B
#define SMEM_GH   (SMEM_WS + 4096)             // gh_s: [2][192] f32 = 1536B
#define SMEM_BH   (SMEM_WS + 4096 + 1536)      // bh_s: [192] f32 = 768B
#define SMEM_SCAN (SMEM_WS + 4096 + 1536 + 768)

__global__ void __cluster_dims__(4, 1, 1) __launch_bounds__(384, 1)
gru_scan(const float* __restrict__ gates, const float* __restrict__ Whh,
         const float* __restrict__ bhh, float* __restrict__ hout)
{
    extern __shared__ char smem_raw[];
    float4* Ws4  = (float4*)smem_raw;               // [chunk][row] : row=g*64+jl
    float*  hbuf = (float*)(smem_raw + SMEM_HB);    // [p][b][256]
    float*  gh_s = (float*)(smem_raw + SMEM_GH);    // [b][192]
    float*  bh_s = (float*)(smem_raw + SMEM_BH);    // [192]

    int tid = threadIdx.x;
    uint32_t rank;
    asm("mov.u32 %0, %%cluster_ctarank;" : "=r"(rank));
    int b0 = (blockIdx.x >> 2) * 2;   // first batch element of this cluster

    // Load W_hh slice: rows {g*256 + rank*64 + jl}, chunk-interleaved layout.
    for (int idx = tid; idx < 192 * 64; idx += 384) {
        int row   = idx >> 6;   // 0..191  (g*64 + jl)
        int chunk = idx & 63;   // k/4
        int g  = row >> 6;
        int jl = row & 63;
        float4 v = *(const float4*)&Whh[(size_t)(g * H_ + rank * 64 + jl) * H_ + chunk * 4];
        Ws4[chunk * 192 + row] = v;
    }
    if (tid < 192) {
        int g = tid >> 6, jl = tid & 63;
        bh_s[tid] = bhh[g * H_ + rank * 64 + jl];
    }
    for (int i = tid; i < 2 * 2 * 256; i += 384) hbuf[i] = 0.0f;
    __syncthreads();
    asm volatile("barrier.cluster.arrive.aligned;" ::: "memory");

    const int b   = tid & 1;     // batch within pair (compute phase)
    const int row = tid >> 1;    // gate-row index 0..191 (compute phase)
    const int jl_e = tid & 63;   // epilogue mapping (threads 0..127)
    const int bb   = (tid >> 6) & 1;
    const int jg   = (int)rank * 64 + jl_e;

    int p = 0;
    for (int t = 0; t < T_; t++) {
        // Prefetch input-side gate pre-activations (independent of h).
        float xr = 0.f, xz = 0.f, xn = 0.f;
        if (tid < 128) {
            const float* gp = &gates[((size_t)(b0 + bb) * T_ + t) * G3];
            xr = __ldg(gp + jg);
            xz = __ldg(gp + 256 + jg);
            xn = __ldg(gp + 512 + jg);
        }

        // Wait for all h_new writes of step t-1 (release-arrive / acquire-wait).
        asm volatile("barrier.cluster.wait.aligned;" ::: "memory");

        // gh[b,row] = sum_k h[b,k] * W[row,k]
        const float4* hb = (const float4*)&hbuf[(p * 2 + b) * 256];
        float a0 = 0.f, a1 = 0.f, a2 = 0.f, a3 = 0.f;
#pragma unroll 8
        for (int ch = 0; ch < 64; ch++) {
            float4 w  = Ws4[ch * 192 + row];
            float4 h4 = hb[ch];
            a0 = fmaf(w.x, h4.x, a0);
            a1 = fmaf(w.y, h4.y, a1);
            a2 = fmaf(w.z, h4.z, a2);
            a3 = fmaf(w.w, h4.w, a3);
        }
        gh_s[b * 192 + row] = (a0 + a1) + (a2 + a3) + bh_s[row];
        __syncthreads();

        if (tid < 128) {
            float r = sigmoidf_(xr + gh_s[bb * 192 + jl_e]);
            float z = sigmoidf_(xz + gh_s[bb * 192 + 64 + jl_e]);
            float n = tanhf_(xn + r * gh_s[bb * 192 + 128 + jl_e]);
            float hold = hbuf[(p * 2 + bb) * 256 + jg];
            float hnew = (1.0f - z) * n + z * hold;

            // Broadcast h_new column to all 4 CTAs' next-phase h buffer.
            uint32_t laddr = (uint32_t)__cvta_generic_to_shared(
                &hbuf[((1 - p) * 2 + bb) * 256 + jg]);
#pragma unroll
            for (uint32_t tc = 0; tc < 4; tc++) {
                asm volatile(
                    "{\n\t.reg .b32 ra;\n\t"
                    "mapa.shared::cluster.u32 ra, %0, %1;\n\t"
                    "st.shared::cluster.f32 [ra], %2;\n\t}"
                    :: "r"(laddr), "r"(tc), "f"(hnew));
            }
            hout[((size_t)(b0 + bb) * T_ + t) * H_ + jg] = hnew;
        }
        asm volatile("barrier.cluster.arrive.aligned;" ::: "memory");
        p ^= 1;
    }
    // Balance arrive/wait and ensure no peer still writes our SMEM at exit.
    asm volatile("barrier.cluster.wait.aligned;" ::: "memory");
}

// ---------------------------------------------------------------------------
extern "C" void kernel_launch(void* const* d_in, const int* in_sizes, int n_in,
                              void* d_out, int out_size)
{
    const float* x    = (const float*)d_in[0];
    const float* Wih0 = (const float*)d_in[1];
    const float* Whh0 = (const float*)d_in[2];
    const float* bih0 = (const float*)d_in[3];
    const float* bhh0 = (const float*)d_in[4];
    const float* Wih1 = (const float*)d_in[5];
    const float* Whh1 = (const float*)d_in[6];
    const float* bih1 = (const float*)d_in[7];
    const float* bhh1 = (const float*)d_in[8];
    const float* fcw  = (const float*)d_in[9];
    const float* fcb  = (const float*)d_in[10];
    float* out = (float*)d_out;

    float *gates, *h;
    cudaGetSymbolAddress((void**)&gates, g_gates);
    cudaGetSymbolAddress((void**)&h, g_h);

    cudaFuncSetAttribute(gru_scan, cudaFuncAttributeMaxDynamicSharedMemorySize,
                         SMEM_SCAN);

    const int M = B_ * T_;
    dim3 blk(256);

    // Layer 0: input GEMM + scan
    gemm_nt<<<dim3(G3 / 64, M / 128), blk>>>(x, Wih0, bih0, gates, M, G3, I_);
    gru_scan<<<128, 384, SMEM_SCAN>>>(gates, Whh0, bhh0, h);

    // Layer 1: input GEMM (from h0) + scan (overwrites h with h1)
    gemm_nt<<<dim3(G3 / 64, M / 128), blk>>>(h, Wih1, bih1, gates, M, G3, H_);
    gru_scan<<<128, 384, SMEM_SCAN>>>(gates, Whh1, bhh1, h);

    // Classifier head
    gemm_nt<<<dim3(C_ / 64, M / 128), blk>>>(h, fcw, fcb, out, M, C_, H_);
}

// round 3
// speedup vs baseline: 1.4151x; 1.4151x over previous
#include <cuda_runtime.h>
#include <cstdint>

#define B_  64
#define T_  2048
#define I_  128
#define H_  256
#define C_  64
#define G3  (3 * H_)   // 768

// Scratch: gates buffer reused by both layers; h buffer reused (h0 then h1).
__device__ float g_gates[(size_t)B_ * T_ * G3];
__device__ float g_h[(size_t)B_ * T_ * H_];

// ---------------------------------------------------------------------------
// GEMM: C[m,n] = sum_k A[m,k] * B[n,k] + bias[n]   (unchanged from R2)
// ---------------------------------------------------------------------------
__global__ void __launch_bounds__(256) gemm_nt(
    const float* __restrict__ A, const float* __restrict__ Bm,
    const float* __restrict__ bias, float* __restrict__ C,
    int M, int N, int K)
{
    const int BM = 128, BN = 64, BK = 16;
    __shared__ float As[BK * BM];
    __shared__ float Bs[BK * BN];

    int tid = threadIdx.x;
    int tx = tid & 15;
    int ty = tid >> 4;
    int m0 = blockIdx.y * BM;
    int n0 = blockIdx.x * BN;

    float acc[8][4];
#pragma unroll
    for (int i = 0; i < 8; i++)
#pragma unroll
        for (int j = 0; j < 4; j++) acc[i][j] = 0.0f;

    for (int kt = 0; kt < K; kt += BK) {
#pragma unroll
        for (int i = 0; i < 2; i++) {
            int idx = tid + i * 256;
            int row = idx >> 2;
            int c4  = idx & 3;
            float4 v = *(const float4*)&A[(size_t)(m0 + row) * K + kt + c4 * 4];
            As[(c4 * 4 + 0) * BM + row] = v.x;
            As[(c4 * 4 + 1) * BM + row] = v.y;
            As[(c4 * 4 + 2) * BM + row] = v.z;
            As[(c4 * 4 + 3) * BM + row] = v.w;
        }
        {
            int row = tid >> 2;
            int c4  = tid & 3;
            float4 v = *(const float4*)&Bm[(size_t)(n0 + row) * K + kt + c4 * 4];
            Bs[(c4 * 4 + 0) * BN + row] = v.x;
            Bs[(c4 * 4 + 1) * BN + row] = v.y;
            Bs[(c4 * 4 + 2) * BN + row] = v.z;
            Bs[(c4 * 4 + 3) * BN + row] = v.w;
        }
        __syncthreads();

#pragma unroll
        for (int k = 0; k < BK; k++) {
            float4 a0 = *(const float4*)&As[k * BM + ty * 8];
            float4 a1 = *(const float4*)&As[k * BM + ty * 8 + 4];
            float4 bq = *(const float4*)&Bs[k * BN + tx * 4];
            float av[8] = {a0.x, a0.y, a0.z, a0.w, a1.x, a1.y, a1.z, a1.w};
            float bv[4] = {bq.x, bq.y, bq.z, bq.w};
#pragma unroll
            for (int i = 0; i < 8; i++)
#pragma unroll
                for (int j = 0; j < 4; j++)
                    acc[i][j] = fmaf(av[i], bv[j], acc[i][j]);
        }
        __syncthreads();
    }

    float4 bv = *(const float4*)&bias[n0 + tx * 4];
#pragma unroll
    for (int i = 0; i < 8; i++) {
        float4 o;
        o.x = acc[i][0] + bv.x;
        o.y = acc[i][1] + bv.y;
        o.z = acc[i][2] + bv.z;
        o.w = acc[i][3] + bv.w;
        *(float4*)&C[(size_t)(m0 + ty * 8 + i) * N + n0 + tx * 4] = o;
    }
}

// ---------------------------------------------------------------------------
// GRU recurrent scan, v2: W_hh entirely in registers, packed f32x2 FMA.
//
// 4-CTA cluster owns 2 batch elements. CTA rank c owns h-columns
// [c*64,(c+1)*64) -> gate rows {j, 256+j, 512+j}. Thread map:
//   row = tid>>1 (0..191), ks = tid&1 (k-half). Each thread holds
//   W[row_g, ks*128 .. ks*128+127] as 64 packed b64 registers.
// h stored batch-interleaved + half-padded:
//   hq[p][half][kk][4] = {h(b0,2k),h(b0,2k+1),h(b1,2k),h(b1,2k+1)}
//   half stride 260 floats (1040 B -> +16 B bank shift, so the two
//   per-warp broadcast addresses (ks=0/1) hit disjoint banks).
// ---------------------------------------------------------------------------
__device__ __forceinline__ float sigmoidf_(float x) {
    return 1.0f / (1.0f + __expf(-x));
}
__device__ __forceinline__ float tanhf_(float x) {
    return 2.0f / (1.0f + __expf(-2.0f * x)) - 1.0f;
}
__device__ __forceinline__ void fma2_(uint64_t& d, uint64_t a, uint64_t b) {
    asm("fma.rn.f32x2 %0, %1, %2, %0;" : "+l"(d) : "l"(a), "l"(b));
}
__device__ __forceinline__ float f2lo_(uint64_t v) {
    float lo, hi;
    asm("mov.b64 {%0,%1}, %2;" : "=f"(lo), "=f"(hi) : "l"(v));
    return lo;
}
__device__ __forceinline__ float f2hi_(uint64_t v) {
    float lo, hi;
    asm("mov.b64 {%0,%1}, %2;" : "=f"(lo), "=f"(hi) : "l"(v));
    return hi;
}

#define HQ_HALF 260          // floats per k-half (64 kk * 4 + 4 pad)
#define HQ_P    (2 * HQ_HALF)  // 520 floats per phase buffer

__global__ void __cluster_dims__(4, 1, 1) __launch_bounds__(384, 1)
gru_scan(const float* __restrict__ gates, const float* __restrict__ Whh,
         const float* __restrict__ bhh, float* __restrict__ hout)
{
    __shared__ float hq[2 * HQ_P];     // [p][half][kk][4]
    __shared__ float gh_s[2 * 192];    // [b][row]
    __shared__ float bh_s[192];

    int tid = threadIdx.x;
    uint32_t rank;
    asm("mov.u32 %0, %%cluster_ctarank;" : "=r"(rank));
    int b0 = (blockIdx.x >> 2) * 2;

    const int row = tid >> 1;          // 0..191 = g*64 + jl
    const int ks  = tid & 1;           // k-half
    const int g   = row >> 6;
    const int jl  = row & 63;
    const int grow = g * H_ + (int)rank * 64 + jl;   // global W_hh row

    // Load this thread's W_hh row-half into 64 packed registers (once).
    uint64_t wr[64];
    const uint64_t* wsrc = (const uint64_t*)&Whh[(size_t)grow * H_ + ks * 128];
#pragma unroll
    for (int kk = 0; kk < 64; kk++) wr[kk] = wsrc[kk];

    if (tid < 192) {
        int gg = tid >> 6, jj = tid & 63;
        bh_s[tid] = bhh[gg * H_ + (int)rank * 64 + jj];
    }
    for (int i = tid; i < 2 * HQ_P; i += 384) hq[i] = 0.0f;
    __syncthreads();
    asm volatile("barrier.cluster.arrive.aligned;" ::: "memory");

    uint32_t hq_u32 = (uint32_t)__cvta_generic_to_shared(hq);
    const uint32_t ks_off = (uint32_t)ks * (HQ_HALF * 4);

    // Epilogue thread mapping (threads 0..127)
    const int jl_e = tid & 63;
    const int bb   = (tid >> 6) & 1;
    const int jg   = (int)rank * 64 + jl_e;
    const int hidx = ((jg >> 7) * HQ_HALF) + (((jg & 127) >> 1) << 2)
                   + bb * 2 + (jg & 1);

    int p = 0;
    for (int t = 0; t < T_; t++) {
        // Prefetch input-side gate pre-activations (independent of h).
        float xr = 0.f, xz = 0.f, xn = 0.f;
        if (tid < 128) {
            const float* gp = &gates[((size_t)(b0 + bb) * T_ + t) * G3];
            xr = __ldg(gp + jg);
            xz = __ldg(gp + 256 + jg);
            xn = __ldg(gp + 512 + jg);
        }

        asm volatile("barrier.cluster.wait.aligned;" ::: "memory");

        // Matvec: gh[b,row] = sum_k h[b,k] * W[row,k], f32x2 over k-pairs.
        uint32_t hb = hq_u32 + (uint32_t)p * (HQ_P * 4) + ks_off;
        uint64_t a00 = 0, a01 = 0, a10 = 0, a11 = 0;
#pragma unroll
        for (int kk = 0; kk < 64; kk += 2) {
            uint64_t hx0, hy0, hx1, hy1;
            asm volatile("ld.shared.v2.u64 {%0,%1}, [%2];"
                         : "=l"(hx0), "=l"(hy0) : "r"(hb + kk * 16));
            asm volatile("ld.shared.v2.u64 {%0,%1}, [%2];"
                         : "=l"(hx1), "=l"(hy1) : "r"(hb + kk * 16 + 16));
            fma2_(a00, wr[kk], hx0);
            fma2_(a10, wr[kk], hy0);
            fma2_(a01, wr[kk + 1], hx1);
            fma2_(a11, wr[kk + 1], hy1);
        }
        float s0 = (f2lo_(a00) + f2hi_(a00)) + (f2lo_(a01) + f2hi_(a01));
        float s1 = (f2lo_(a10) + f2hi_(a10)) + (f2lo_(a11) + f2hi_(a11));
        s0 += __shfl_xor_sync(0xffffffffu, s0, 1);
        s1 += __shfl_xor_sync(0xffffffffu, s1, 1);
        if (ks == 0) {
            float bh = bh_s[row];
            gh_s[row]       = s0 + bh;
            gh_s[192 + row] = s1 + bh;
        }
        __syncthreads();

        if (tid < 128) {
            float r = sigmoidf_(xr + gh_s[bb * 192 + jl_e]);
            float z = sigmoidf_(xz + gh_s[bb * 192 + 64 + jl_e]);
            float n = tanhf_(xn + r * gh_s[bb * 192 + 128 + jl_e]);
            float hold = hq[p * HQ_P + hidx];
            float hnew = (1.0f - z) * n + z * hold;

            uint32_t laddr = hq_u32 + (uint32_t)((1 - p) * HQ_P + hidx) * 4;
#pragma unroll
            for (uint32_t tc = 0; tc < 4; tc++) {
                asm volatile(
                    "{\n\t.reg .b32 ra;\n\t"
                    "mapa.shared::cluster.u32 ra, %0, %1;\n\t"
                    "st.shared::cluster.f32 [ra], %2;\n\t}"
                    :: "r"(laddr), "r"(tc), "f"(hnew));
            }
            hout[((size_t)(b0 + bb) * T_ + t) * H_ + jg] = hnew;
        }
        asm volatile("barrier.cluster.arrive.aligned;" ::: "memory");
        p ^= 1;
    }
    asm volatile("barrier.cluster.wait.aligned;" ::: "memory");
}

// ---------------------------------------------------------------------------
extern "C" void kernel_launch(void* const* d_in, const int* in_sizes, int n_in,
                              void* d_out, int out_size)
{
    const float* x    = (const float*)d_in[0];
    const float* Wih0 = (const float*)d_in[1];
    const float* Whh0 = (const float*)d_in[2];
    const float* bih0 = (const float*)d_in[3];
    const float* bhh0 = (const float*)d_in[4];
    const float* Wih1 = (const float*)d_in[5];
    const float* Whh1 = (const float*)d_in[6];
    const float* bih1 = (const float*)d_in[7];
    const float* bhh1 = (const float*)d_in[8];
    const float* fcw  = (const float*)d_in[9];
    const float* fcb  = (const float*)d_in[10];
    float* out = (float*)d_out;

    float *gates, *h;
    cudaGetSymbolAddress((void**)&gates, g_gates);
    cudaGetSymbolAddress((void**)&h, g_h);

    const int M = B_ * T_;
    dim3 blk(256);

    // Layer 0
    gemm_nt<<<dim3(G3 / 64, M / 128), blk>>>(x, Wih0, bih0, gates, M, G3, I_);
    gru_scan<<<128, 384>>>(gates, Whh0, bhh0, h);

    // Layer 1
    gemm_nt<<<dim3(G3 / 64, M / 128), blk>>>(h, Wih1, bih1, gates, M, G3, H_);
    gru_scan<<<128, 384>>>(gates, Whh1, bhh1, h);

    // Classifier head
    gemm_nt<<<dim3(C_ / 64, M / 128), blk>>>(h, fcw, fcb, out, M, C_, H_);
}

// round 4
// speedup vs baseline: 1.7413x; 1.2305x over previous
#include <cuda_runtime.h>
#include <cstdint>

#define B_  64
#define T_  2048
#define I_  128
#define H_  256
#define C_  64
#define G3  (3 * H_)   // 768

__device__ float g_gates[(size_t)B_ * T_ * G3];
__device__ float g_h[(size_t)B_ * T_ * H_];

// ---------------------------------------------------------------------------
// helpers
// ---------------------------------------------------------------------------
__device__ __forceinline__ float sigmoidf_(float x) {
    return 1.0f / (1.0f + __expf(-x));
}
__device__ __forceinline__ float tanhf_(float x) {
    return 2.0f / (1.0f + __expf(-2.0f * x)) - 1.0f;
}
__device__ __forceinline__ void fma2_(uint64_t& d, uint64_t a, uint64_t b) {
    asm("fma.rn.f32x2 %0, %1, %2, %0;" : "+l"(d) : "l"(a), "l"(b));
}
__device__ __forceinline__ float f2lo_(uint64_t v) {
    float lo, hi;
    asm("mov.b64 {%0,%1}, %2;" : "=f"(lo), "=f"(hi) : "l"(v));
    return lo;
}
__device__ __forceinline__ float f2hi_(uint64_t v) {
    float lo, hi;
    asm("mov.b64 {%0,%1}, %2;" : "=f"(lo), "=f"(hi) : "l"(v));
    return hi;
}
__device__ __forceinline__ uint64_t dup2_(float x) {
    uint64_t r;
    asm("mov.b64 %0, {%1,%1};" : "=l"(r) : "f"(x));
    return r;
}
__device__ __forceinline__ void mbar_init_(uint32_t a, uint32_t cnt) {
    asm volatile("mbarrier.init.shared.b64 [%0], %1;" :: "r"(a), "r"(cnt) : "memory");
}
__device__ __forceinline__ void mbar_arm_(uint32_t a, uint32_t tx) {
    asm volatile("mbarrier.arrive.expect_tx.shared.b64 _, [%0], %1;"
                 :: "r"(a), "r"(tx) : "memory");
}
__device__ __forceinline__ void mbar_wait_(uint32_t a, uint32_t par) {
    uint32_t done;
    asm volatile(
        "{\n\t.reg .pred p;\n\t"
        "mbarrier.try_wait.parity.acquire.cta.shared::cta.b64 p, [%1], %2;\n\t"
        "selp.b32 %0, 1, 0, p;\n\t}"
        : "=r"(done) : "r"(a), "r"(par) : "memory");
    if (!done) {
        asm volatile(
            "{\n\t.reg .pred P1;\n\t"
            "W_%=:\n\t"
            "mbarrier.try_wait.parity.acquire.cta.shared::cta.b64 P1, [%0], %1, 0x989680;\n\t"
            "@P1 bra.uni D_%=;\n\t"
            "bra.uni W_%=;\n\t"
            "D_%=:\n\t}"
            :: "r"(a), "r"(par) : "memory");
    }
}

// ---------------------------------------------------------------------------
// GEMM: C[m,n] = sum_k A[m,k] * B[n,k] + bias[n]
// BM=128, BN=64, BK=16, 256 threads; f32x2 inner (acc packed over m-pairs).
// ---------------------------------------------------------------------------
__global__ void __launch_bounds__(256) gemm_nt(
    const float* __restrict__ A, const float* __restrict__ Bm,
    const float* __restrict__ bias, float* __restrict__ C,
    int M, int N, int K)
{
    const int BM = 128, BN = 64, BK = 16;
    __shared__ float As[BK * BM];
    __shared__ float Bs[BK * BN];

    int tid = threadIdx.x;
    int tx = tid & 15;
    int ty = tid >> 4;
    int m0 = blockIdx.y * BM;
    int n0 = blockIdx.x * BN;

    uint64_t acc2[4][4];   // acc2[ii][j] = {row 2ii, row 2ii+1}
#pragma unroll
    for (int i = 0; i < 4; i++)
#pragma unroll
        for (int j = 0; j < 4; j++) acc2[i][j] = 0ull;

    for (int kt = 0; kt < K; kt += BK) {
#pragma unroll
        for (int i = 0; i < 2; i++) {
            int idx = tid + i * 256;
            int row = idx >> 2;
            int c4  = idx & 3;
            float4 v = *(const float4*)&A[(size_t)(m0 + row) * K + kt + c4 * 4];
            As[(c4 * 4 + 0) * BM + row] = v.x;
            As[(c4 * 4 + 1) * BM + row] = v.y;
            As[(c4 * 4 + 2) * BM + row] = v.z;
            As[(c4 * 4 + 3) * BM + row] = v.w;
        }
        {
            int row = tid >> 2;
            int c4  = tid & 3;
            float4 v = *(const float4*)&Bm[(size_t)(n0 + row) * K + kt + c4 * 4];
            Bs[(c4 * 4 + 0) * BN + row] = v.x;
            Bs[(c4 * 4 + 1) * BN + row] = v.y;
            Bs[(c4 * 4 + 2) * BN + row] = v.z;
            Bs[(c4 * 4 + 3) * BN + row] = v.w;
        }
        __syncthreads();

#pragma unroll
        for (int k = 0; k < BK; k++) {
            const uint64_t* a2 = (const uint64_t*)&As[k * BM + ty * 8];
            uint64_t av0 = a2[0], av1 = a2[1], av2 = a2[2], av3 = a2[3];
            float4 bq = *(const float4*)&Bs[k * BN + tx * 4];
            uint64_t b0 = dup2_(bq.x), b1 = dup2_(bq.y);
            uint64_t b2 = dup2_(bq.z), b3 = dup2_(bq.w);
            fma2_(acc2[0][0], av0, b0); fma2_(acc2[0][1], av0, b1);
            fma2_(acc2[0][2], av0, b2); fma2_(acc2[0][3], av0, b3);
            fma2_(acc2[1][0], av1, b0); fma2_(acc2[1][1], av1, b1);
            fma2_(acc2[1][2], av1, b2); fma2_(acc2[1][3], av1, b3);
            fma2_(acc2[2][0], av2, b0); fma2_(acc2[2][1], av2, b1);
            fma2_(acc2[2][2], av2, b2); fma2_(acc2[2][3], av2, b3);
            fma2_(acc2[3][0], av3, b0); fma2_(acc2[3][1], av3, b1);
            fma2_(acc2[3][2], av3, b2); fma2_(acc2[3][3], av3, b3);
        }
        __syncthreads();
    }

    float4 bv = *(const float4*)&bias[n0 + tx * 4];
#pragma unroll
    for (int ii = 0; ii < 4; ii++) {
        float4 oe, oo;
        oe.x = f2lo_(acc2[ii][0]) + bv.x;
        oe.y = f2lo_(acc2[ii][1]) + bv.y;
        oe.z = f2lo_(acc2[ii][2]) + bv.z;
        oe.w = f2lo_(acc2[ii][3]) + bv.w;
        oo.x = f2hi_(acc2[ii][0]) + bv.x;
        oo.y = f2hi_(acc2[ii][1]) + bv.y;
        oo.z = f2hi_(acc2[ii][2]) + bv.z;
        oo.w = f2hi_(acc2[ii][3]) + bv.w;
        *(float4*)&C[(size_t)(m0 + ty * 8 + 2 * ii) * N + n0 + tx * 4] = oe;
        *(float4*)&C[(size_t)(m0 + ty * 8 + 2 * ii + 1) * N + n0 + tx * 4] = oo;
    }
}

// ---------------------------------------------------------------------------
// GRU recurrent scan, v3: mbarrier + st.async sync fabric (no cluster barrier
// in the step loop). W_hh in registers, f32x2 matvec (unchanged from R3).
// ---------------------------------------------------------------------------
#define HQ_HALF 260            // floats per k-half (64 kk * 4 + 4 pad)
#define HQ_P    (2 * HQ_HALF)  // 520 floats per phase buffer
#define TXB     2048u          // 512 h floats * 4B received per CTA per step

__global__ void __cluster_dims__(4, 1, 1) __launch_bounds__(384, 1)
gru_scan(const float* __restrict__ gates, const float* __restrict__ Whh,
         const float* __restrict__ bhh, float* __restrict__ hout)
{
    __shared__ float hq[2 * HQ_P];     // [p][half][kk][4]
    __shared__ float gh_s[2 * 192];    // [b][row]
    __shared__ float bh_s[192];
    __shared__ __align__(8) uint64_t mbar_s[2];

    int tid = threadIdx.x;
    uint32_t rank;
    asm("mov.u32 %0, %%cluster_ctarank;" : "=r"(rank));
    int b0 = (blockIdx.x >> 2) * 2;

    const int row = tid >> 1;          // 0..191 = g*64 + jl
    const int ks  = tid & 1;           // k-half
    const int g   = row >> 6;
    const int jl  = row & 63;
    const int grow = g * H_ + (int)rank * 64 + jl;

    // W_hh row-half -> 64 packed b64 registers (once).
    uint64_t wr[64];
    const uint64_t* wsrc = (const uint64_t*)&Whh[(size_t)grow * H_ + ks * 128];
#pragma unroll
    for (int kk = 0; kk < 64; kk++) wr[kk] = wsrc[kk];

    uint32_t hq_u32   = (uint32_t)__cvta_generic_to_shared(hq);
    uint32_t mbar_u32 = (uint32_t)__cvta_generic_to_shared(mbar_s);

    if (tid < 192) {
        int gg = tid >> 6, jj = tid & 63;
        bh_s[tid] = bhh[gg * H_ + (int)rank * 64 + jj];
    }
    for (int i = tid; i < 2 * HQ_P; i += 384) hq[i] = 0.0f;
    if (tid == 0) {
        mbar_init_(mbar_u32, 1);
        mbar_init_(mbar_u32 + 8, 1);
        mbar_arm_(mbar_u32 + 8, TXB);   // arm mbar[1] for step-0 writes
    }
    __syncthreads();
    asm volatile("barrier.cluster.arrive.aligned;" ::: "memory");
    asm volatile("barrier.cluster.wait.aligned;" ::: "memory");

    const uint32_t ks_off = (uint32_t)ks * (HQ_HALF * 4);

    // Epilogue mapping (threads 0..127)
    const int jl_e = tid & 63;
    const int bb   = (tid >> 6) & 1;
    const int jg   = (int)rank * 64 + jl_e;
    const int hidx = ((jg >> 7) * HQ_HALF) + (((jg & 127) >> 1) << 2)
                   + bb * 2 + (jg & 1);

    uint32_t ph = 0;   // parity bits for mbar[0], mbar[1]
    for (int t = 0; t < T_; t++) {
        const int buf = t & 1;
        const int nxt = buf ^ 1;

        // Prefetch gates_x (independent of h; hidden under wait+matvec).
        float xr = 0.f, xz = 0.f, xn = 0.f;
        if (tid < 128) {
            const float* gp = &gates[((size_t)(b0 + bb) * T_ + t) * G3];
            xr = __ldg(gp + jg);
            xz = __ldg(gp + 256 + jg);
            xn = __ldg(gp + 512 + jg);
        }

        if (t) {
            mbar_wait_(mbar_u32 + buf * 8, (ph >> buf) & 1u);
            ph ^= (1u << buf);
        }
        // Re-arm this buffer's barrier for its use at step t+2. Safe: any
        // step-(t+1) writer must first pass mbar[nxt], which requires OUR
        // step-t writes, which come after this arm in program order.
        if (tid == 0) mbar_arm_(mbar_u32 + buf * 8, TXB);

        // Matvec: gh[b,row] = sum_k h[b,k] * W[row,k]  (f32x2 over k-pairs)
        uint32_t hb = hq_u32 + (uint32_t)buf * (HQ_P * 4) + ks_off;
        uint64_t a00 = 0, a01 = 0, a10 = 0, a11 = 0;
#pragma unroll
        for (int kk = 0; kk < 64; kk += 2) {
            uint64_t hx0, hy0, hx1, hy1;
            asm volatile("ld.shared.v2.u64 {%0,%1}, [%2];"
                         : "=l"(hx0), "=l"(hy0) : "r"(hb + kk * 16));
            asm volatile("ld.shared.v2.u64 {%0,%1}, [%2];"
                         : "=l"(hx1), "=l"(hy1) : "r"(hb + kk * 16 + 16));
            fma2_(a00, wr[kk], hx0);
            fma2_(a10, wr[kk], hy0);
            fma2_(a01, wr[kk + 1], hx1);
            fma2_(a11, wr[kk + 1], hy1);
        }
        float s0 = (f2lo_(a00) + f2hi_(a00)) + (f2lo_(a01) + f2hi_(a01));
        float s1 = (f2lo_(a10) + f2hi_(a10)) + (f2lo_(a11) + f2hi_(a11));
        s0 += __shfl_xor_sync(0xffffffffu, s0, 1);
        s1 += __shfl_xor_sync(0xffffffffu, s1, 1);
        if (ks == 0) {
            float bh = bh_s[row];
            gh_s[row]       = s0 + bh;
            gh_s[192 + row] = s1 + bh;
        }
        __syncthreads();

        if (tid < 128) {
            float r = sigmoidf_(xr + gh_s[bb * 192 + jl_e]);
            float z = sigmoidf_(xz + gh_s[bb * 192 + 64 + jl_e]);
            float n = tanhf_(xn + r * gh_s[bb * 192 + 128 + jl_e]);
            float hold = hq[buf * HQ_P + hidx];
            float hnew = (1.0f - z) * n + z * hold;

            // Remote store + tx-completion to every CTA's next-phase buffer.
            uint32_t dst = hq_u32 + (uint32_t)(nxt * HQ_P + hidx) * 4;
            uint32_t mb  = mbar_u32 + nxt * 8;
#pragma unroll
            for (uint32_t tc = 0; tc < 4; tc++) {
                asm volatile(
                    "{\n\t.reg .b32 ra, rb;\n\t"
                    "mapa.shared::cluster.u32 ra, %0, %2;\n\t"
                    "mapa.shared::cluster.u32 rb, %1, %2;\n\t"
                    "st.async.shared::cluster.mbarrier::complete_tx::bytes.f32 "
                    "[ra], %3, [rb];\n\t}"
                    :: "r"(dst), "r"(mb), "r"(tc), "f"(hnew) : "memory");
            }
            hout[((size_t)(b0 + bb) * T_ + t) * H_ + jg] = hnew;
        }
        // No block barrier here: mbar[nxt] is the inter-step sync.
    }

    // Drain: ensure all inbound st.async to our SMEM landed before exit.
    mbar_wait_(mbar_u32, ph & 1u);
    asm volatile("barrier.cluster.arrive.aligned;" ::: "memory");
    asm volatile("barrier.cluster.wait.aligned;" ::: "memory");
}

// ---------------------------------------------------------------------------
extern "C" void kernel_launch(void* const* d_in, const int* in_sizes, int n_in,
                              void* d_out, int out_size)
{
    const float* x    = (const float*)d_in[0];
    const float* Wih0 = (const float*)d_in[1];
    const float* Whh0 = (const float*)d_in[2];
    const float* bih0 = (const float*)d_in[3];
    const float* bhh0 = (const float*)d_in[4];
    const float* Wih1 = (const float*)d_in[5];
    const float* Whh1 = (const float*)d_in[6];
    const float* bih1 = (const float*)d_in[7];
    const float* bhh1 = (const float*)d_in[8];
    const float* fcw  = (const float*)d_in[9];
    const float* fcb  = (const float*)d_in[10];
    float* out = (float*)d_out;

    float *gates, *h;
    cudaGetSymbolAddress((void**)&gates, g_gates);
    cudaGetSymbolAddress((void**)&h, g_h);

    const int M = B_ * T_;
    dim3 blk(256);

    gemm_nt<<<dim3(G3 / 64, M / 128), blk>>>(x, Wih0, bih0, gates, M, G3, I_);
    gru_scan<<<128, 384>>>(gates, Whh0, bhh0, h);

    gemm_nt<<<dim3(G3 / 64, M / 128), blk>>>(h, Wih1, bih1, gates, M, G3, H_);
    gru_scan<<<128, 384>>>(gates, Whh1, bhh1, h);

    gemm_nt<<<dim3(C_ / 64, M / 128), blk>>>(h, fcw, fcb, out, M, C_, H_);
}

// round 5
// speedup vs baseline: 1.7430x; 1.0010x over previous
#include <cuda_runtime.h>
#include <cstdint>

#define B_  64
#define T_  2048
#define I_  128
#define H_  256
#define C_  64
#define G3  (3 * H_)   // 768

__device__ float g_gates[(size_t)B_ * T_ * G3];
__device__ float g_h[(size_t)B_ * T_ * H_];

// ---------------------------------------------------------------------------
// helpers
// ---------------------------------------------------------------------------
__device__ __forceinline__ float sigmoidf_(float x) {
    return 1.0f / (1.0f + __expf(-x));
}
__device__ __forceinline__ float tanhf_(float x) {
    return 2.0f / (1.0f + __expf(-2.0f * x)) - 1.0f;
}
__device__ __forceinline__ void fma2_(uint64_t& d, uint64_t a, uint64_t b) {
    asm("fma.rn.f32x2 %0, %1, %2, %0;" : "+l"(d) : "l"(a), "l"(b));
}
__device__ __forceinline__ float f2lo_(uint64_t v) {
    float lo, hi;
    asm("mov.b64 {%0,%1}, %2;" : "=f"(lo), "=f"(hi) : "l"(v));
    return lo;
}
__device__ __forceinline__ float f2hi_(uint64_t v) {
    float lo, hi;
    asm("mov.b64 {%0,%1}, %2;" : "=f"(lo), "=f"(hi) : "l"(v));
    return hi;
}
__device__ __forceinline__ uint64_t dup2_(float x) {
    uint64_t r;
    asm("mov.b64 %0, {%1,%1};" : "=l"(r) : "f"(x));
    return r;
}
__device__ __forceinline__ void mbar_init_(uint32_t a, uint32_t cnt) {
    asm volatile("mbarrier.init.shared.b64 [%0], %1;" :: "r"(a), "r"(cnt) : "memory");
}
__device__ __forceinline__ void mbar_arm_(uint32_t a, uint32_t tx) {
    asm volatile("mbarrier.arrive.expect_tx.shared.b64 _, [%0], %1;"
                 :: "r"(a), "r"(tx) : "memory");
}
__device__ __forceinline__ void mbar_wait_(uint32_t a, uint32_t par) {
    uint32_t done;
    asm volatile(
        "{\n\t.reg .pred p;\n\t"
        "mbarrier.try_wait.parity.acquire.cta.shared::cta.b64 p, [%1], %2;\n\t"
        "selp.b32 %0, 1, 0, p;\n\t}"
        : "=r"(done) : "r"(a), "r"(par) : "memory");
    if (!done) {
        asm volatile(
            "{\n\t.reg .pred P1;\n\t"
            "W_%=:\n\t"
            "mbarrier.try_wait.parity.acquire.cta.shared::cta.b64 P1, [%0], %1, 0x989680;\n\t"
            "@P1 bra.uni D_%=;\n\t"
            "bra.uni W_%=;\n\t"
            "D_%=:\n\t}"
            :: "r"(a), "r"(par) : "memory");
    }
}

// ---------------------------------------------------------------------------
// GEMM: C[m,n] = sum_k A[m,k] * B[n,k] + bias[n]
// BM=128, BN=64, BK=16, 256 threads; f32x2 inner; double-buffered SMEM
// (one __syncthreads per k-tile, LDG of next tile hidden under compute).
// ---------------------------------------------------------------------------
__global__ void __launch_bounds__(256) gemm_nt(
    const float* __restrict__ A, const float* __restrict__ Bm,
    const float* __restrict__ bias, float* __restrict__ C,
    int M, int N, int K)
{
    const int BM = 128, BN = 64, BK = 16;
    __shared__ float As[2][BK * BM];
    __shared__ float Bs[2][BK * BN];

    int tid = threadIdx.x;
    int tx = tid & 15;
    int ty = tid >> 4;
    int m0 = blockIdx.y * BM;
    int n0 = blockIdx.x * BN;

    // staging indices
    const int a_row0 = tid >> 2,        a_c4 = tid & 3;          // +0, +64 rows
    const int b_row  = tid >> 2,        b_c4 = tid & 3;

    uint64_t acc2[4][4];
#pragma unroll
    for (int i = 0; i < 4; i++)
#pragma unroll
        for (int j = 0; j < 4; j++) acc2[i][j] = 0ull;

    float4 a_stg0, a_stg1, b_stg;

    // load tile 0
    a_stg0 = *(const float4*)&A[(size_t)(m0 + a_row0) * K + a_c4 * 4];
    a_stg1 = *(const float4*)&A[(size_t)(m0 + a_row0 + 64) * K + a_c4 * 4];
    b_stg  = *(const float4*)&Bm[(size_t)(n0 + b_row) * K + b_c4 * 4];
    {
        float* as = As[0]; float* bs = Bs[0];
        as[(a_c4 * 4 + 0) * BM + a_row0] = a_stg0.x;
        as[(a_c4 * 4 + 1) * BM + a_row0] = a_stg0.y;
        as[(a_c4 * 4 + 2) * BM + a_row0] = a_stg0.z;
        as[(a_c4 * 4 + 3) * BM + a_row0] = a_stg0.w;
        as[(a_c4 * 4 + 0) * BM + a_row0 + 64] = a_stg1.x;
        as[(a_c4 * 4 + 1) * BM + a_row0 + 64] = a_stg1.y;
        as[(a_c4 * 4 + 2) * BM + a_row0 + 64] = a_stg1.z;
        as[(a_c4 * 4 + 3) * BM + a_row0 + 64] = a_stg1.w;
        bs[(b_c4 * 4 + 0) * BN + b_row] = b_stg.x;
        bs[(b_c4 * 4 + 1) * BN + b_row] = b_stg.y;
        bs[(b_c4 * 4 + 2) * BN + b_row] = b_stg.z;
        bs[(b_c4 * 4 + 3) * BN + b_row] = b_stg.w;
    }
    __syncthreads();

    int p = 0;
    for (int kt = 0; kt < K; kt += BK) {
        const bool has_next = (kt + BK) < K;
        if (has_next) {
            a_stg0 = *(const float4*)&A[(size_t)(m0 + a_row0) * K + kt + BK + a_c4 * 4];
            a_stg1 = *(const float4*)&A[(size_t)(m0 + a_row0 + 64) * K + kt + BK + a_c4 * 4];
            b_stg  = *(const float4*)&Bm[(size_t)(n0 + b_row) * K + kt + BK + b_c4 * 4];
        }

        const float* as = As[p];
        const float* bs = Bs[p];
#pragma unroll
        for (int k = 0; k < BK; k++) {
            const uint64_t* a2 = (const uint64_t*)&as[k * BM + ty * 8];
            uint64_t av0 = a2[0], av1 = a2[1], av2 = a2[2], av3 = a2[3];
            float4 bq = *(const float4*)&bs[k * BN + tx * 4];
            uint64_t b0 = dup2_(bq.x), b1 = dup2_(bq.y);
            uint64_t b2 = dup2_(bq.z), b3 = dup2_(bq.w);
            fma2_(acc2[0][0], av0, b0); fma2_(acc2[0][1], av0, b1);
            fma2_(acc2[0][2], av0, b2); fma2_(acc2[0][3], av0, b3);
            fma2_(acc2[1][0], av1, b0); fma2_(acc2[1][1], av1, b1);
            fma2_(acc2[1][2], av1, b2); fma2_(acc2[1][3], av1, b3);
            fma2_(acc2[2][0], av2, b0); fma2_(acc2[2][1], av2, b1);
            fma2_(acc2[2][2], av2, b2); fma2_(acc2[2][3], av2, b3);
            fma2_(acc2[3][0], av3, b0); fma2_(acc2[3][1], av3, b1);
            fma2_(acc2[3][2], av3, b2); fma2_(acc2[3][3], av3, b3);
        }

        if (has_next) {
            float* asn = As[p ^ 1]; float* bsn = Bs[p ^ 1];
            asn[(a_c4 * 4 + 0) * BM + a_row0] = a_stg0.x;
            asn[(a_c4 * 4 + 1) * BM + a_row0] = a_stg0.y;
            asn[(a_c4 * 4 + 2) * BM + a_row0] = a_stg0.z;
            asn[(a_c4 * 4 + 3) * BM + a_row0] = a_stg0.w;
            asn[(a_c4 * 4 + 0) * BM + a_row0 + 64] = a_stg1.x;
            asn[(a_c4 * 4 + 1) * BM + a_row0 + 64] = a_stg1.y;
            asn[(a_c4 * 4 + 2) * BM + a_row0 + 64] = a_stg1.z;
            asn[(a_c4 * 4 + 3) * BM + a_row0 + 64] = a_stg1.w;
            bsn[(b_c4 * 4 + 0) * BN + b_row] = b_stg.x;
            bsn[(b_c4 * 4 + 1) * BN + b_row] = b_stg.y;
            bsn[(b_c4 * 4 + 2) * BN + b_row] = b_stg.z;
            bsn[(b_c4 * 4 + 3) * BN + b_row] = b_stg.w;
            __syncthreads();
        }
        p ^= 1;
    }

    float4 bv = *(const float4*)&bias[n0 + tx * 4];
#pragma unroll
    for (int ii = 0; ii < 4; ii++) {
        float4 oe, oo;
        oe.x = f2lo_(acc2[ii][0]) + bv.x;
        oe.y = f2lo_(acc2[ii][1]) + bv.y;
        oe.z = f2lo_(acc2[ii][2]) + bv.z;
        oe.w = f2lo_(acc2[ii][3]) + bv.w;
        oo.x = f2hi_(acc2[ii][0]) + bv.x;
        oo.y = f2hi_(acc2[ii][1]) + bv.y;
        oo.z = f2hi_(acc2[ii][2]) + bv.z;
        oo.w = f2hi_(acc2[ii][3]) + bv.w;
        *(float4*)&C[(size_t)(m0 + ty * 8 + 2 * ii) * N + n0 + tx * 4] = oe;
        *(float4*)&C[(size_t)(m0 + ty * 8 + 2 * ii + 1) * N + n0 + tx * 4] = oo;
    }
}

// ---------------------------------------------------------------------------
// GRU recurrent scan, v4: de-phased batches. The two batch elements of a
// cluster run half a step apart with independent mbarriers and h buffers;
// each batch's sync/epilogue/DSMEM latency hides under the other's matvec.
//
// h layout per batch: [phase][ks-half][k-pair] floats; half stride 132 floats
// (528 B -> +16 B bank shift so ks=0/ks=1 warp broadcasts hit disjoint banks).
// ---------------------------------------------------------------------------
#define HB_HALF 132            // floats per ks-half (128 + 4 pad)
#define HB_P    (2 * HB_HALF)  // 264 floats per phase
#define HB_B    (2 * HB_P)     // 528 floats per batch
#define TXB     1024u          // 256 h floats * 4B per CTA per batch-step

__global__ void __cluster_dims__(4, 1, 1) __launch_bounds__(384, 1)
gru_scan(const float* __restrict__ gates, const float* __restrict__ Whh,
         const float* __restrict__ bhh, float* __restrict__ hout)
{
    __shared__ float hq[2 * HB_B];     // [b][p][half][kpair]
    __shared__ float gh_s[2 * 192];    // [b][row]
    __shared__ float bh_s[192];
    __shared__ __align__(8) uint64_t mbar_s[4];   // [b][buf]

    int tid = threadIdx.x;
    uint32_t rank;
    asm("mov.u32 %0, %%cluster_ctarank;" : "=r"(rank));
    int b0 = (blockIdx.x >> 2) * 2;

    const int row = tid >> 1;          // 0..191 = g*64 + jl
    const int ks  = tid & 1;           // k-half
    const int g   = row >> 6;
    const int jl  = row & 63;
    const int grow = g * H_ + (int)rank * 64 + jl;

    // W_hh row-half -> 64 packed b64 registers (once).
    uint64_t wr[64];
    const uint64_t* wsrc = (const uint64_t*)&Whh[(size_t)grow * H_ + ks * 128];
#pragma unroll
    for (int kk = 0; kk < 64; kk++) wr[kk] = wsrc[kk];

    uint32_t hq_u32   = (uint32_t)__cvta_generic_to_shared(hq);
    uint32_t mbar_u32 = (uint32_t)__cvta_generic_to_shared(mbar_s);

    if (tid < 192) {
        int gg = tid >> 6, jj = tid & 63;
        bh_s[tid] = bhh[gg * H_ + (int)rank * 64 + jj];
    }
    for (int i = tid; i < 2 * HB_B; i += 384) hq[i] = 0.0f;
    if (tid == 0) {
#pragma unroll
        for (int m = 0; m < 4; m++) mbar_init_(mbar_u32 + m * 8, 1);
        mbar_arm_(mbar_u32 + 1 * 8, TXB);   // mb[0][1] for step-0 writes
        mbar_arm_(mbar_u32 + 3 * 8, TXB);   // mb[1][1]
    }
    __syncthreads();
    asm volatile("barrier.cluster.arrive.aligned;" ::: "memory");
    asm volatile("barrier.cluster.wait.aligned;" ::: "memory");

    const uint32_t ks_off = (uint32_t)ks * (HB_HALF * 4);

    // Epilogue mapping (threads 0..127): bb selects which half-step this
    // thread's epilogue belongs to.
    const int jl_e = tid & 63;
    const int bb   = (tid >> 6) & 1;
    const int jg   = (int)rank * 64 + jl_e;
    const int hidx = (jg >> 7) * HB_HALF + (jg & 127);  // float idx in phase

    uint32_t ph = 0;   // parity bits: bit (b*2+buf)
    for (int t = 0; t < T_; t++) {
        const int buf = t & 1;
        const int nxt = buf ^ 1;

        // Prefetch gates_x for this thread's (bb, jg) — used in its epilogue.
        float xr = 0.f, xz = 0.f, xn = 0.f;
        if (tid < 128) {
            const float* gp = &gates[((size_t)(b0 + bb) * T_ + t) * G3];
            xr = __ldg(gp + jg);
            xz = __ldg(gp + 256 + jg);
            xn = __ldg(gp + 512 + jg);
        }

#pragma unroll
        for (int b = 0; b < 2; b++) {
            const int m = b * 2 + buf;
            if (t) {
                mbar_wait_(mbar_u32 + m * 8, (ph >> m) & 1u);
                ph ^= (1u << m);
            }
            // Re-arm for use at step t+2 (safe: t+1 writers must first pass
            // mb[b][nxt], which needs our step-t stores, issued below).
            if (tid == 0) mbar_arm_(mbar_u32 + m * 8, TXB);

            // Matvec for batch b: gh[b,row] = sum_k h[b,k] * W[row,k]
            uint32_t hb = hq_u32 + (uint32_t)(b * HB_B + buf * HB_P) * 4 + ks_off;
            uint64_t a0 = 0, a1 = 0;
#pragma unroll
            for (int kk = 0; kk < 64; kk += 2) {
                uint64_t hx, hy;
                asm volatile("ld.shared.v2.u64 {%0,%1}, [%2];"
                             : "=l"(hx), "=l"(hy) : "r"(hb + kk * 8));
                fma2_(a0, wr[kk], hx);
                fma2_(a1, wr[kk + 1], hy);
            }
            float s = (f2lo_(a0) + f2hi_(a0)) + (f2lo_(a1) + f2hi_(a1));
            s += __shfl_xor_sync(0xffffffffu, s, 1);
            if (ks == 0) gh_s[b * 192 + row] = s + bh_s[row];
            __syncthreads();

            if (tid < 128 && bb == b) {
                float r = sigmoidf_(xr + gh_s[b * 192 + jl_e]);
                float z = sigmoidf_(xz + gh_s[b * 192 + 64 + jl_e]);
                float n = tanhf_(xn + r * gh_s[b * 192 + 128 + jl_e]);
                float hold = hq[b * HB_B + buf * HB_P + hidx];
                float hnew = (1.0f - z) * n + z * hold;

                uint32_t dst = hq_u32 + (uint32_t)(b * HB_B + nxt * HB_P + hidx) * 4;
                uint32_t mb  = mbar_u32 + (b * 2 + nxt) * 8;
#pragma unroll
                for (uint32_t tc = 0; tc < 4; tc++) {
                    asm volatile(
                        "{\n\t.reg .b32 ra, rb;\n\t"
                        "mapa.shared::cluster.u32 ra, %0, %2;\n\t"
                        "mapa.shared::cluster.u32 rb, %1, %2;\n\t"
                        "st.async.shared::cluster.mbarrier::complete_tx::bytes.f32 "
                        "[ra], %3, [rb];\n\t}"
                        :: "r"(dst), "r"(mb), "r"(tc), "f"(hnew) : "memory");
                }
                hout[((size_t)(b0 + bb) * T_ + t) * H_ + jg] = hnew;
            }
        }
    }

    // Drain inbound st.async before exit.
    mbar_wait_(mbar_u32 + 0 * 8, (ph >> 0) & 1u);
    mbar_wait_(mbar_u32 + 2 * 8, (ph >> 2) & 1u);
    asm volatile("barrier.cluster.arrive.aligned;" ::: "memory");
    asm volatile("barrier.cluster.wait.aligned;" ::: "memory");
}

// ---------------------------------------------------------------------------
extern "C" void kernel_launch(void* const* d_in, const int* in_sizes, int n_in,
                              void* d_out, int out_size)
{
    const float* x    = (const float*)d_in[0];
    const float* Wih0 = (const float*)d_in[1];
    const float* Whh0 = (const float*)d_in[2];
    const float* bih0 = (const float*)d_in[3];
    const float* bhh0 = (const float*)d_in[4];
    const float* Wih1 = (const float*)d_in[5];
    const float* Whh1 = (const float*)d_in[6];
    const float* bih1 = (const float*)d_in[7];
    const float* bhh1 = (const float*)d_in[8];
    const float* fcw  = (const float*)d_in[9];
    const float* fcb  = (const float*)d_in[10];
    float* out = (float*)d_out;

    float *gates, *h;
    cudaGetSymbolAddress((void**)&gates, g_gates);
    cudaGetSymbolAddress((void**)&h, g_h);

    const int M = B_ * T_;
    dim3 blk(256);

    gemm_nt<<<dim3(G3 / 64, M / 128), blk>>>(x, Wih0, bih0, gates, M, G3, I_);
    gru_scan<<<128, 384>>>(gates, Whh0, bhh0, h);

    gemm_nt<<<dim3(G3 / 64, M / 128), blk>>>(h, Wih1, bih1, gates, M, G3, H_);
    gru_scan<<<128, 384>>>(gates, Whh1, bhh1, h);

    gemm_nt<<<dim3(C_ / 64, M / 128), blk>>>(h, fcw, fcb, out, M, C_, H_);
}